// round 3
// baseline (speedup 1.0000x reference)
#include <cuda_runtime.h>
#include <cstdint>

#define N_NODES 50000
#define N_EDGES 500000
#define EMB     128
#define HALF_N  25000
#define HALF_ELEMS 3200000u
#define INV_KEEP (1.0f/0.9f)

// Scatter-sum accumulator (static __device__ scratch: allowed; no runtime alloc)
__device__ float g_acc[(size_t)N_NODES * EMB];

typedef unsigned long long ull;

// ---------- packed f32x2 helpers (sm_100+ fma.rn.f32x2) ----------
__device__ __forceinline__ ull pack2(float lo, float hi) {
    ull r; asm("mov.b64 %0, {%1, %2};" : "=l"(r) : "f"(lo), "f"(hi)); return r;
}
__device__ __forceinline__ void unpack2(ull v, float& lo, float& hi) {
    asm("mov.b64 {%0, %1}, %2;" : "=f"(lo), "=f"(hi) : "l"(v));
}
__device__ __forceinline__ ull ffma2(ull a, ull b, ull c) {
    ull d; asm("fma.rn.f32x2 %0, %1, %2, %3;" : "=l"(d) : "l"(a), "l"(b), "l"(c));
    return d;
}
// vectorized global fp32 reduction (sm_90+)
__device__ __forceinline__ void red_add_v4(float* addr, float4 v) {
    asm volatile("red.global.add.v4.f32 [%0], {%1, %2, %3, %4};"
                 :: "l"(addr), "f"(v.x), "f"(v.y), "f"(v.z), "f"(v.w) : "memory");
}

// ---------- JAX threefry2x32, key = jax.random.key(42) = (0, 42) ----------
__device__ __forceinline__ void tf2x32_42(unsigned ctr0, unsigned ctr1,
                                          unsigned& o0, unsigned& o1) {
    const unsigned k0 = 0u, k1 = 42u;
    const unsigned k2 = k0 ^ k1 ^ 0x1BD11BDAu;
    unsigned x0 = ctr0 + k0, x1 = ctr1 + k1;
#define TF_R(r) { x0 += x1; x1 = __funnelshift_l(x1, x1, (r)); x1 ^= x0; }
#define TF_G0   TF_R(13) TF_R(15) TF_R(26) TF_R(6)
#define TF_G1   TF_R(17) TF_R(29) TF_R(16) TF_R(24)
    TF_G0; x0 += k1; x1 += k2 + 1u;
    TF_G1; x0 += k2; x1 += k0 + 2u;
    TF_G0; x0 += k0; x1 += k1 + 3u;
    TF_G1; x0 += k1; x1 += k2 + 4u;
    TF_G0; x0 += k2; x1 += k0 + 5u;
#undef TF_R
#undef TF_G0
#undef TF_G1
    o0 = x0; o1 = x1;
}
__device__ __forceinline__ float tf_uniform(unsigned bits) {
    return __uint_as_float((bits >> 9) | 0x3f800000u) - 1.0f;
}
// jax_threefry_partitionable=True (default in modern JAX): per-element bits
// for linear index i (< 2^32): threefry2x32(key, ctr=(0, i)), out = x0 ^ x1.
__device__ __forceinline__ unsigned tf_bits_partitionable(unsigned idx) {
    unsigned a, b;
    tf2x32_42(0u, idx, a, b);
    return a ^ b;
}

// ---------- K0: acc = boundary_condition (self-loop messages) ----------
__global__ void k0_init(const float* __restrict__ boundary) {
    int i = blockIdx.x * blockDim.x + threadIdx.x;
    if (i < N_NODES * EMB / 4)
        reinterpret_cast<float4*>(g_acc)[i] =
            reinterpret_cast<const float4*>(boundary)[i];
}

// ---------- K1: per-edge message GEMM (E x 192 @ 192 x 128) + relu + scatter ----------
// Tile: 64 edges x 128 cols, K tiled by 64. 256 threads; thread = (tr 0..7, tc 0..31);
// each thread owns 8 edges (4 f32x2 pairs) x 4 cols.
#define K1_SMEM ((64*64 + 64*128) * 4 + 2*64*4)

__global__ void __launch_bounds__(256, 2) k1_msg(
    const float* __restrict__ hidden, const int* __restrict__ eidx,
    const float* __restrict__ eattr,  const float* __restrict__ etime,
    const float* __restrict__ Wm,     const float* __restrict__ bm)
{
    extern __shared__ float sm[];
    float* As = sm;                 // [64][64]  k-major: As[k*64 + e]
    float* Bs = sm + 64 * 64;       // [64][128]
    int*   sidx = (int*)(sm + 64 * 64 + 64 * 128);  // src[64], dst[64]

    const int t  = threadIdx.x;
    const int tr = t >> 5, tc = t & 31;
    const int e0 = blockIdx.x * 64;

    if (t < 64) {
        int e = e0 + t;
        sidx[t]      = (e < N_EDGES) ? eidx[e] : 0;
        sidx[64 + t] = (e < N_EDGES) ? eidx[N_EDGES + e] : -1;
    }

    float4 bmv = *(const float4*)&bm[tc * 4];
    ull acc[4][4];
#pragma unroll
    for (int p = 0; p < 4; ++p) {
        acc[p][0] = pack2(bmv.x, bmv.x); acc[p][1] = pack2(bmv.y, bmv.y);
        acc[p][2] = pack2(bmv.z, bmv.z); acc[p][3] = pack2(bmv.w, bmv.w);
    }
    __syncthreads();

    const int le  = t & 63;
    const int ge  = e0 + le;
    const int gec = (ge < N_EDGES) ? ge : (N_EDGES - 1);

    for (int kt = 0; kt < 3; ++kt) {
        if (kt) __syncthreads();
        // B tile: W_msg rows [kt*64, kt*64+64) — 2048 float4, 8 per thread
        const float4* Wq = (const float4*)(Wm + kt * 64 * EMB);
#pragma unroll
        for (int i = 0; i < 8; ++i) {
            int idx = t + i * 256;
            int r = idx >> 5, q = idx & 31;
            *(float4*)&Bs[r * EMB + q * 4] = Wq[r * 32 + q];
        }
        // A tile: gather+transpose. (e = t&63, quad q = (t>>6)+4j)
        int src = sidx[le];
#pragma unroll
        for (int j = 0; j < 4; ++j) {
            int q = (t >> 6) + j * 4;   // 0..15 -> k-local q*4..q*4+3
            float4 v;
            if (kt < 2)     v = *(const float4*)&hidden[(size_t)src * EMB + kt * 64 + q * 4];
            else if (q < 8) v = *(const float4*)&eattr[(size_t)gec * 32 + q * 4];
            else            v = *(const float4*)&etime[(size_t)gec * 32 + (q - 8) * 4];
            As[(q * 4 + 0) * 64 + le] = v.x;
            As[(q * 4 + 1) * 64 + le] = v.y;
            As[(q * 4 + 2) * 64 + le] = v.z;
            As[(q * 4 + 3) * 64 + le] = v.w;
        }
        __syncthreads();

#pragma unroll 8
        for (int k = 0; k < 64; ++k) {
            const ulonglong2* ap = (const ulonglong2*)&As[k * 64 + tr * 8];
            ulonglong2 a01 = ap[0], a23 = ap[1];
            float4 b = *(const float4*)&Bs[k * EMB + tc * 4];
            ull b0 = pack2(b.x, b.x), b1 = pack2(b.y, b.y);
            ull b2 = pack2(b.z, b.z), b3 = pack2(b.w, b.w);
            ull a[4] = {a01.x, a01.y, a23.x, a23.y};
#pragma unroll
            for (int p = 0; p < 4; ++p) {
                acc[p][0] = ffma2(a[p], b0, acc[p][0]);
                acc[p][1] = ffma2(a[p], b1, acc[p][1]);
                acc[p][2] = ffma2(a[p], b2, acc[p][2]);
                acc[p][3] = ffma2(a[p], b3, acc[p][3]);
            }
        }
    }

    // epilogue: relu + vectorized scatter-add
#pragma unroll
    for (int p = 0; p < 4; ++p) {
        int e  = tr * 8 + 2 * p;
        int d0 = sidx[64 + e], d1 = sidx[64 + e + 1];
        float4 v0, v1; float lo, hi;
        unpack2(acc[p][0], lo, hi); v0.x = fmaxf(lo, 0.f); v1.x = fmaxf(hi, 0.f);
        unpack2(acc[p][1], lo, hi); v0.y = fmaxf(lo, 0.f); v1.y = fmaxf(hi, 0.f);
        unpack2(acc[p][2], lo, hi); v0.z = fmaxf(lo, 0.f); v1.z = fmaxf(hi, 0.f);
        unpack2(acc[p][3], lo, hi); v0.w = fmaxf(lo, 0.f); v1.w = fmaxf(hi, 0.f);
        if (d0 >= 0) red_add_v4(&g_acc[(size_t)d0 * EMB + tc * 4], v0);
        if (d1 >= 0) red_add_v4(&g_acc[(size_t)d1 * EMB + tc * 4], v1);
    }
}

// ---------- K2: node GEMM (50K x 128 @ 128 x 128) + LN + relu + dropout ----------
// Tile: 64 rows = 32 "low" rows (base..base+31) interleaved with rows +25000.
// local row lr -> global row base+(lr>>1) + (lr&1)*25000.
#define K2_SMEM ((128*64 + 128*128) * 4)

__global__ void __launch_bounds__(256) k2_node(
    const float* __restrict__ Wl, const float* __restrict__ bl,
    const float* __restrict__ gamma, const float* __restrict__ beta,
    float* __restrict__ out)
{
    extern __shared__ float sm[];
    float* As = sm;              // [128][64] k-major
    float* Bs = sm + 128 * 64;   // [128][128]

    const int t  = threadIdx.x;
    const int tr = t >> 5, tc = t & 31;
    const int base = blockIdx.x * 32;

    // B tile: full W_lin (128x128), 4096 float4, 16 per thread
#pragma unroll
    for (int i = 0; i < 16; ++i) {
        int idx = t + i * 256;
        int r = idx >> 5, q = idx & 31;
        *(float4*)&Bs[r * EMB + q * 4] = *(const float4*)&Wl[r * EMB + q * 4];
    }
    // A tile: 64 rows x 32 quads, 8 per thread, transpose to k-major
    {
        int lr = t & 63;
        int pr = base + (lr >> 1);
        int grow = ((pr < HALF_N) ? pr : (HALF_N - 1)) + ((lr & 1) ? HALF_N : 0);
#pragma unroll
        for (int j = 0; j < 8; ++j) {
            int q = (t >> 6) * 8 + j;
            float4 v = *(const float4*)&g_acc[(size_t)grow * EMB + q * 4];
            As[(q * 4 + 0) * 64 + lr] = v.x;
            As[(q * 4 + 1) * 64 + lr] = v.y;
            As[(q * 4 + 2) * 64 + lr] = v.z;
            As[(q * 4 + 3) * 64 + lr] = v.w;
        }
    }
    float4 blv = *(const float4*)&bl[tc * 4];
    ull acc[4][4];
#pragma unroll
    for (int p = 0; p < 4; ++p) {
        acc[p][0] = pack2(blv.x, blv.x); acc[p][1] = pack2(blv.y, blv.y);
        acc[p][2] = pack2(blv.z, blv.z); acc[p][3] = pack2(blv.w, blv.w);
    }
    __syncthreads();

#pragma unroll 8
    for (int k = 0; k < 128; ++k) {
        const ulonglong2* ap = (const ulonglong2*)&As[k * 64 + tr * 8];
        ulonglong2 a01 = ap[0], a23 = ap[1];
        float4 b = *(const float4*)&Bs[k * EMB + tc * 4];
        ull b0 = pack2(b.x, b.x), b1 = pack2(b.y, b.y);
        ull b2 = pack2(b.z, b.z), b3 = pack2(b.w, b.w);
        ull a[4] = {a01.x, a01.y, a23.x, a23.y};
#pragma unroll
        for (int p = 0; p < 4; ++p) {
            acc[p][0] = ffma2(a[p], b0, acc[p][0]);
            acc[p][1] = ffma2(a[p], b1, acc[p][1]);
            acc[p][2] = ffma2(a[p], b2, acc[p][2]);
            acc[p][3] = ffma2(a[p], b3, acc[p][3]);
        }
    }

    float4 gv = *(const float4*)&gamma[tc * 4];
    float4 bv = *(const float4*)&beta[tc * 4];
    float ga[4] = {gv.x, gv.y, gv.z, gv.w};
    float be[4] = {bv.x, bv.y, bv.z, bv.w};

#pragma unroll
    for (int p = 0; p < 4; ++p) {
        float lo[4], hi[4];
#pragma unroll
        for (int j = 0; j < 4; ++j) unpack2(acc[p][j], lo[j], hi[j]);

        float s0 = lo[0] + lo[1] + lo[2] + lo[3];
        float q0 = lo[0]*lo[0] + lo[1]*lo[1] + lo[2]*lo[2] + lo[3]*lo[3];
        float s1 = hi[0] + hi[1] + hi[2] + hi[3];
        float q1 = hi[0]*hi[0] + hi[1]*hi[1] + hi[2]*hi[2] + hi[3]*hi[3];
#pragma unroll
        for (int off = 16; off; off >>= 1) {
            s0 += __shfl_xor_sync(0xffffffffu, s0, off);
            q0 += __shfl_xor_sync(0xffffffffu, q0, off);
            s1 += __shfl_xor_sync(0xffffffffu, s1, off);
            q1 += __shfl_xor_sync(0xffffffffu, q1, off);
        }
        float m0 = s0 * (1.0f / EMB);
        float r0 = rsqrtf(q0 * (1.0f / EMB) - m0 * m0 + 1e-5f);
        float m1 = s1 * (1.0f / EMB);
        float r1 = rsqrtf(q1 * (1.0f / EMB) - m1 * m1 + 1e-5f);

        int rlow = base + tr * 4 + p;          // low row (< 25000 when valid)
        float o0[4], o1[4];
#pragma unroll
        for (int j = 0; j < 4; ++j) {
            float y0 = fmaxf((lo[j] - m0) * r0 * ga[j] + be[j], 0.f);
            float y1 = fmaxf((hi[j] - m1) * r1 * ga[j] + be[j], 0.f);
            // partitionable threefry: per-element counter = 64-bit linear index
            unsigned idx0 = (unsigned)(rlow * EMB + tc * 4 + j);   // row rlow
            unsigned idx1 = idx0 + HALF_ELEMS;                     // row rlow+25000
            o0[j] = (tf_uniform(tf_bits_partitionable(idx0)) < 0.9f) ? y0 * INV_KEEP : 0.f;
            o1[j] = (tf_uniform(tf_bits_partitionable(idx1)) < 0.9f) ? y1 * INV_KEEP : 0.f;
        }
        if (rlow < HALF_N) {
            *(float4*)&out[(size_t)rlow * EMB + tc * 4] =
                make_float4(o0[0], o0[1], o0[2], o0[3]);
            *(float4*)&out[(size_t)(rlow + HALF_N) * EMB + tc * 4] =
                make_float4(o1[0], o1[1], o1[2], o1[3]);
        }
    }
}

// ---------- launch ----------
extern "C" void kernel_launch(void* const* d_in, const int* in_sizes, int n_in,
                              void* d_out, int out_size) {
    (void)in_sizes; (void)n_in; (void)out_size;
    const float* hidden = (const float*)d_in[0];
    const int*   eidx   = (const int*)  d_in[1];
    const float* eattr  = (const float*)d_in[2];
    const float* etime  = (const float*)d_in[3];
    const float* bc     = (const float*)d_in[4];
    const float* Wm     = (const float*)d_in[5];
    const float* bm     = (const float*)d_in[6];
    const float* Wl     = (const float*)d_in[7];
    const float* bl     = (const float*)d_in[8];
    const float* gam    = (const float*)d_in[9];
    const float* bet    = (const float*)d_in[10];
    float* out = (float*)d_out;

    cudaFuncSetAttribute((const void*)k1_msg,
                         cudaFuncAttributeMaxDynamicSharedMemorySize, K1_SMEM);
    cudaFuncSetAttribute((const void*)k2_node,
                         cudaFuncAttributeMaxDynamicSharedMemorySize, K2_SMEM);

    k0_init<<<(N_NODES * EMB / 4 + 255) / 256, 256>>>(bc);
    k1_msg<<<(N_EDGES + 63) / 64, 256, K1_SMEM>>>(hidden, eidx, eattr, etime, Wm, bm);
    k2_node<<<(HALF_N + 31) / 32, 256, K2_SMEM>>>(Wl, bl, gam, bet, out);
}

// round 8
// speedup vs baseline: 1.8637x; 1.8637x over previous
#include <cuda_runtime.h>
#include <cuda_bf16.h>
#include <cstdint>

#define N_NODES 50000
#define N_EDGES 500000
#define EMB     128
#define HALF_N  25000
#define HALF_ELEMS 3200000u
#define INV_KEEP (1.0f/0.9f)

__device__ float g_acc[(size_t)N_NODES * EMB];   // scatter accumulator
__device__ float g_hid[(size_t)N_NODES * EMB];   // H' = hidden @ Wh + b

typedef unsigned long long ull;

// ---------- packed f32x2 helpers ----------
__device__ __forceinline__ ull pack2(float lo, float hi) {
    ull r; asm("mov.b64 %0, {%1, %2};" : "=l"(r) : "f"(lo), "f"(hi)); return r;
}
__device__ __forceinline__ void unpack2(ull v, float& lo, float& hi) {
    asm("mov.b64 {%0, %1}, %2;" : "=f"(lo), "=f"(hi) : "l"(v));
}
__device__ __forceinline__ ull ffma2(ull a, ull b, ull c) {
    ull d; asm("fma.rn.f32x2 %0, %1, %2, %3;" : "=l"(d) : "l"(a), "l"(b), "l"(c));
    return d;
}
__device__ __forceinline__ void red_add_v4(float* addr, float4 v) {
    asm volatile("red.global.add.v4.f32 [%0], {%1, %2, %3, %4};"
                 :: "l"(addr), "f"(v.x), "f"(v.y), "f"(v.z), "f"(v.w) : "memory");
}

// ---------- JAX threefry2x32, key (0,42), partitionable ----------
__device__ __forceinline__ void tf2x32_42(unsigned c0, unsigned c1, unsigned& o0, unsigned& o1) {
    const unsigned k0 = 0u, k1 = 42u, k2 = 0x1BD11BDAu ^ 42u;
    unsigned x0 = c0 + k0, x1 = c1 + k1;
#define TF_R(r) { x0 += x1; x1 = __funnelshift_l(x1, x1, (r)); x1 ^= x0; }
#define TF_G0   TF_R(13) TF_R(15) TF_R(26) TF_R(6)
#define TF_G1   TF_R(17) TF_R(29) TF_R(16) TF_R(24)
    TF_G0; x0 += k1; x1 += k2 + 1u;
    TF_G1; x0 += k2; x1 += k0 + 2u;
    TF_G0; x0 += k0; x1 += k1 + 3u;
    TF_G1; x0 += k1; x1 += k2 + 4u;
    TF_G0; x0 += k2; x1 += k0 + 5u;
#undef TF_R
#undef TF_G0
#undef TF_G1
    o0 = x0; o1 = x1;
}
__device__ __forceinline__ float tf_uniform(unsigned b) {
    return __uint_as_float((b >> 9) | 0x3f800000u) - 1.0f;
}
__device__ __forceinline__ unsigned tf_bits_part(unsigned idx) {
    unsigned a, b; tf2x32_42(0u, idx, a, b); return a ^ b;
}

// ================= K0: acc = boundary ==================
__global__ void k0_init(const float* __restrict__ boundary) {
    int i = blockIdx.x * blockDim.x + threadIdx.x;
    if (i < N_NODES * EMB / 4)
        reinterpret_cast<float4*>(g_acc)[i] =
            reinterpret_cast<const float4*>(boundary)[i];
}

// ================= KP: H' = hidden @ Wm[0:128] + bm ==================
// Tile 128 rows x 128 cols, K=128. 256 threads; thread (te=tid>>4, tc=tid&15)
// owns rows te*8..+8 (4 f32x2 pairs), cols tc*8..+8.
#define KP_SMEM ((128*128 + 128*128) * 4)

__global__ void __launch_bounds__(256, 1) kp_hid(
    const float* __restrict__ hidden, const float* __restrict__ Wm,
    const float* __restrict__ bm)
{
    extern __shared__ float sm[];
    float* As = sm;              // [128k][128row]
    float* Bs = sm + 128 * 128;  // [128k][128col]

    const int t = threadIdx.x;
    const int base = blockIdx.x * 128;

    // Bs = Wm rows 0..127 (already [k][n] layout) — linear copy
#pragma unroll
    for (int i = 0; i < 16; ++i)
        ((float4*)Bs)[t + i * 256] = ((const float4*)Wm)[t + i * 256];

    // As: transpose-stage. thread: row lr = t&127, k-half = t>>7
    {
        int lr = t & 127;
        int gr = base + lr; if (gr >= N_NODES) gr = N_NODES - 1;
        const float* hrow = &hidden[(size_t)gr * EMB];
#pragma unroll
        for (int j = 0; j < 16; ++j) {
            int k0 = (t >> 7) * 64 + j * 4;
            float4 v = *(const float4*)&hrow[k0];
            As[(k0 + 0) * 128 + lr] = v.x;
            As[(k0 + 1) * 128 + lr] = v.y;
            As[(k0 + 2) * 128 + lr] = v.z;
            As[(k0 + 3) * 128 + lr] = v.w;
        }
    }
    __syncthreads();

    const int te = t >> 4, tc = t & 15;
    float4 b0 = *(const float4*)&bm[tc * 8];
    float4 b1 = *(const float4*)&bm[tc * 8 + 4];
    ull acc[4][8];
#pragma unroll
    for (int er = 0; er < 4; ++er) {
        acc[er][0] = pack2(b0.x, b0.x); acc[er][1] = pack2(b0.y, b0.y);
        acc[er][2] = pack2(b0.z, b0.z); acc[er][3] = pack2(b0.w, b0.w);
        acc[er][4] = pack2(b1.x, b1.x); acc[er][5] = pack2(b1.y, b1.y);
        acc[er][6] = pack2(b1.z, b1.z); acc[er][7] = pack2(b1.w, b1.w);
    }

#pragma unroll 4
    for (int k = 0; k < 128; ++k) {
        const ulonglong2* ap = (const ulonglong2*)&As[k * 128 + te * 8];
        ulonglong2 a01 = ap[0], a23 = ap[1];
        float4 q0 = *(const float4*)&Bs[k * 128 + tc * 8];
        float4 q1 = *(const float4*)&Bs[k * 128 + tc * 8 + 4];
        ull bp[8] = {pack2(q0.x, q0.x), pack2(q0.y, q0.y), pack2(q0.z, q0.z), pack2(q0.w, q0.w),
                     pack2(q1.x, q1.x), pack2(q1.y, q1.y), pack2(q1.z, q1.z), pack2(q1.w, q1.w)};
        ull a[4] = {a01.x, a01.y, a23.x, a23.y};
#pragma unroll
        for (int er = 0; er < 4; ++er)
#pragma unroll
            for (int c = 0; c < 8; ++c)
                acc[er][c] = ffma2(a[er], bp[c], acc[er][c]);
    }

#pragma unroll
    for (int er = 0; er < 4; ++er) {
        int r0 = base + te * 8 + er * 2;
        float lo[8], hi[8];
#pragma unroll
        for (int c = 0; c < 8; ++c) unpack2(acc[er][c], lo[c], hi[c]);
        if (r0 < N_NODES) {
            *(float4*)&g_hid[(size_t)r0 * EMB + tc * 8]     = make_float4(lo[0], lo[1], lo[2], lo[3]);
            *(float4*)&g_hid[(size_t)r0 * EMB + tc * 8 + 4] = make_float4(lo[4], lo[5], lo[6], lo[7]);
        }
        if (r0 + 1 < N_NODES) {
            *(float4*)&g_hid[(size_t)(r0 + 1) * EMB + tc * 8]     = make_float4(hi[0], hi[1], hi[2], hi[3]);
            *(float4*)&g_hid[(size_t)(r0 + 1) * EMB + tc * 8 + 4] = make_float4(hi[4], hi[5], hi[6], hi[7]);
        }
    }
}

// ================= K1: edge GEMM (E x 64 @ 64 x 128) + H' gather + relu + scatter ==
// Tile 128 edges x 128 cols, K=64 ([ea|et] @ Wm[128:192]).
#define K1_SMEM ((64*128 + 64*128) * 4 + 2*128*4)
#define NUM_TILES ((N_EDGES + 127) / 128)

__global__ void __launch_bounds__(256, 2) k1_msg(
    const int* __restrict__ eidx, const float* __restrict__ eattr,
    const float* __restrict__ etime, const float* __restrict__ Wm)
{
    extern __shared__ float sm[];
    float* As = sm;               // [64k][128edge]
    float* Bs = sm + 64 * 128;    // [64k][128col]
    int* src_s = (int*)(sm + 2 * 64 * 128);
    int* dst_s = src_s + 128;

    const int t = threadIdx.x;
    const int e0 = blockIdx.x * 128;

    // Bs = Wm rows 128..191 — linear copy (2048 float4)
    {
        const float4* Wq = (const float4*)(Wm + 128 * EMB);
#pragma unroll
        for (int i = 0; i < 8; ++i)
            ((float4*)Bs)[t + i * 256] = Wq[t + i * 256];
    }
    // edge indices
    if (t < 128) {
        int e = e0 + t;
        src_s[t] = (e < N_EDGES) ? eidx[e] : 0;
    } else {
        int e = e0 + t - 128;
        dst_s[t - 128] = (e < N_EDGES) ? eidx[N_EDGES + e] : -1;
    }
    // As: gather edge features, transpose. thread: edge e=t&127, sel=t>>7
    {
        int e = t & 127;
        int ge = e0 + e;
        int gec = (ge < N_EDGES) ? ge : (N_EDGES - 1);
        int sel = t >> 7;
        const float* ptr = sel ? &etime[(size_t)gec * 32] : &eattr[(size_t)gec * 32];
        int koff = sel * 32;
#pragma unroll
        for (int j = 0; j < 8; ++j) {
            float4 v = *(const float4*)&ptr[j * 4];
            As[(koff + j * 4 + 0) * 128 + e] = v.x;
            As[(koff + j * 4 + 1) * 128 + e] = v.y;
            As[(koff + j * 4 + 2) * 128 + e] = v.z;
            As[(koff + j * 4 + 3) * 128 + e] = v.w;
        }
    }
    __syncthreads();

    const int te = t >> 4, tc = t & 15;
    ull acc[4][8];
#pragma unroll
    for (int er = 0; er < 4; ++er)
#pragma unroll
        for (int c = 0; c < 8; ++c) acc[er][c] = 0ull;

#pragma unroll 4
    for (int k = 0; k < 64; ++k) {
        const ulonglong2* ap = (const ulonglong2*)&As[k * 128 + te * 8];
        ulonglong2 a01 = ap[0], a23 = ap[1];
        float4 q0 = *(const float4*)&Bs[k * 128 + tc * 8];
        float4 q1 = *(const float4*)&Bs[k * 128 + tc * 8 + 4];
        ull bp[8] = {pack2(q0.x, q0.x), pack2(q0.y, q0.y), pack2(q0.z, q0.z), pack2(q0.w, q0.w),
                     pack2(q1.x, q1.x), pack2(q1.y, q1.y), pack2(q1.z, q1.z), pack2(q1.w, q1.w)};
        ull a[4] = {a01.x, a01.y, a23.x, a23.y};
#pragma unroll
        for (int er = 0; er < 4; ++er)
#pragma unroll
            for (int c = 0; c < 8; ++c)
                acc[er][c] = ffma2(a[er], bp[c], acc[er][c]);
    }

    // epilogue: msg = relu(H'[src] + acc); scatter-add to g_acc[dst]
#pragma unroll
    for (int er = 0; er < 4; ++er) {
        float lo[8], hi[8];
#pragma unroll
        for (int c = 0; c < 8; ++c) unpack2(acc[er][c], lo[c], hi[c]);
        int el = te * 8 + er * 2;
#pragma unroll
        for (int half = 0; half < 2; ++half) {
            int e = el + half;
            float* v = half ? hi : lo;
            int sidx = src_s[e];
            int d = dst_s[e];
            const float* hp = &g_hid[(size_t)sidx * EMB + tc * 8];
            float4 h0 = *(const float4*)hp;
            float4 h1 = *(const float4*)(hp + 4);
            float4 o0 = make_float4(fmaxf(v[0] + h0.x, 0.f), fmaxf(v[1] + h0.y, 0.f),
                                    fmaxf(v[2] + h0.z, 0.f), fmaxf(v[3] + h0.w, 0.f));
            float4 o1 = make_float4(fmaxf(v[4] + h1.x, 0.f), fmaxf(v[5] + h1.y, 0.f),
                                    fmaxf(v[6] + h1.z, 0.f), fmaxf(v[7] + h1.w, 0.f));
            if (d >= 0) {
                float* base = &g_acc[(size_t)d * EMB + tc * 8];
                red_add_v4(base, o0);
                red_add_v4(base + 4, o1);
            }
        }
    }
}

// ================= K2: node GEMM + LN + relu + dropout (unchanged, passing) =========
#define K2_SMEM ((128*64 + 128*128) * 4)

__global__ void __launch_bounds__(256) k2_node(
    const float* __restrict__ Wl, const float* __restrict__ bl,
    const float* __restrict__ gamma, const float* __restrict__ beta,
    float* __restrict__ out)
{
    extern __shared__ float sm[];
    float* As = sm;              // [128][64] k-major
    float* Bs = sm + 128 * 64;   // [128][128]

    const int t  = threadIdx.x;
    const int tr = t >> 5, tc = t & 31;
    const int base = blockIdx.x * 32;

#pragma unroll
    for (int i = 0; i < 16; ++i) {
        int idx = t + i * 256;
        int r = idx >> 5, q = idx & 31;
        *(float4*)&Bs[r * EMB + q * 4] = *(const float4*)&Wl[r * EMB + q * 4];
    }
    {
        int lr = t & 63;
        int pr = base + (lr >> 1);
        int grow = ((pr < HALF_N) ? pr : (HALF_N - 1)) + ((lr & 1) ? HALF_N : 0);
#pragma unroll
        for (int j = 0; j < 8; ++j) {
            int q = (t >> 6) * 8 + j;
            float4 v = *(const float4*)&g_acc[(size_t)grow * EMB + q * 4];
            As[(q * 4 + 0) * 64 + lr] = v.x;
            As[(q * 4 + 1) * 64 + lr] = v.y;
            As[(q * 4 + 2) * 64 + lr] = v.z;
            As[(q * 4 + 3) * 64 + lr] = v.w;
        }
    }
    float4 blv = *(const float4*)&bl[tc * 4];
    ull acc[4][4];
#pragma unroll
    for (int p = 0; p < 4; ++p) {
        acc[p][0] = pack2(blv.x, blv.x); acc[p][1] = pack2(blv.y, blv.y);
        acc[p][2] = pack2(blv.z, blv.z); acc[p][3] = pack2(blv.w, blv.w);
    }
    __syncthreads();

#pragma unroll 8
    for (int k = 0; k < 128; ++k) {
        const ulonglong2* ap = (const ulonglong2*)&As[k * 64 + tr * 8];
        ulonglong2 a01 = ap[0], a23 = ap[1];
        float4 b = *(const float4*)&Bs[k * EMB + tc * 4];
        ull b0 = pack2(b.x, b.x), b1 = pack2(b.y, b.y);
        ull b2 = pack2(b.z, b.z), b3 = pack2(b.w, b.w);
        ull a[4] = {a01.x, a01.y, a23.x, a23.y};
#pragma unroll
        for (int p = 0; p < 4; ++p) {
            acc[p][0] = ffma2(a[p], b0, acc[p][0]);
            acc[p][1] = ffma2(a[p], b1, acc[p][1]);
            acc[p][2] = ffma2(a[p], b2, acc[p][2]);
            acc[p][3] = ffma2(a[p], b3, acc[p][3]);
        }
    }

    float4 gv = *(const float4*)&gamma[tc * 4];
    float4 bv = *(const float4*)&beta[tc * 4];
    float ga[4] = {gv.x, gv.y, gv.z, gv.w};
    float be[4] = {bv.x, bv.y, bv.z, bv.w};

#pragma unroll
    for (int p = 0; p < 4; ++p) {
        float lo[4], hi[4];
#pragma unroll
        for (int j = 0; j < 4; ++j) unpack2(acc[p][j], lo[j], hi[j]);

        float s0 = lo[0] + lo[1] + lo[2] + lo[3];
        float q0 = lo[0]*lo[0] + lo[1]*lo[1] + lo[2]*lo[2] + lo[3]*lo[3];
        float s1 = hi[0] + hi[1] + hi[2] + hi[3];
        float q1 = hi[0]*hi[0] + hi[1]*hi[1] + hi[2]*hi[2] + hi[3]*hi[3];
#pragma unroll
        for (int off = 16; off; off >>= 1) {
            s0 += __shfl_xor_sync(0xffffffffu, s0, off);
            q0 += __shfl_xor_sync(0xffffffffu, q0, off);
            s1 += __shfl_xor_sync(0xffffffffu, s1, off);
            q1 += __shfl_xor_sync(0xffffffffu, q1, off);
        }
        float m0 = s0 * (1.0f / EMB);
        float r0 = rsqrtf(q0 * (1.0f / EMB) - m0 * m0 + 1e-5f);
        float m1 = s1 * (1.0f / EMB);
        float r1 = rsqrtf(q1 * (1.0f / EMB) - m1 * m1 + 1e-5f);

        int rlow = base + tr * 4 + p;
        float o0[4], o1[4];
#pragma unroll
        for (int j = 0; j < 4; ++j) {
            float y0 = fmaxf((lo[j] - m0) * r0 * ga[j] + be[j], 0.f);
            float y1 = fmaxf((hi[j] - m1) * r1 * ga[j] + be[j], 0.f);
            unsigned idx0 = (unsigned)(rlow * EMB + tc * 4 + j);
            unsigned idx1 = idx0 + HALF_ELEMS;
            o0[j] = (tf_uniform(tf_bits_part(idx0)) < 0.9f) ? y0 * INV_KEEP : 0.f;
            o1[j] = (tf_uniform(tf_bits_part(idx1)) < 0.9f) ? y1 * INV_KEEP : 0.f;
        }
        if (rlow < HALF_N) {
            *(float4*)&out[(size_t)rlow * EMB + tc * 4] =
                make_float4(o0[0], o0[1], o0[2], o0[3]);
            *(float4*)&out[(size_t)(rlow + HALF_N) * EMB + tc * 4] =
                make_float4(o1[0], o1[1], o1[2], o1[3]);
        }
    }
}

// ================= launch ==================
extern "C" void kernel_launch(void* const* d_in, const int* in_sizes, int n_in,
                              void* d_out, int out_size) {
    (void)in_sizes; (void)n_in; (void)out_size;
    const float* hidden = (const float*)d_in[0];
    const int*   eidx   = (const int*)  d_in[1];
    const float* eattr  = (const float*)d_in[2];
    const float* etime  = (const float*)d_in[3];
    const float* bc     = (const float*)d_in[4];
    const float* Wm     = (const float*)d_in[5];
    const float* bm     = (const float*)d_in[6];
    const float* Wl     = (const float*)d_in[7];
    const float* bl     = (const float*)d_in[8];
    const float* gam    = (const float*)d_in[9];
    const float* bet    = (const float*)d_in[10];
    float* out = (float*)d_out;

    cudaFuncSetAttribute((const void*)kp_hid,
                         cudaFuncAttributeMaxDynamicSharedMemorySize, KP_SMEM);
    cudaFuncSetAttribute((const void*)k1_msg,
                         cudaFuncAttributeMaxDynamicSharedMemorySize, K1_SMEM);
    cudaFuncSetAttribute((const void*)k2_node,
                         cudaFuncAttributeMaxDynamicSharedMemorySize, K2_SMEM);

    k0_init<<<(N_NODES * EMB / 4 + 255) / 256, 256>>>(bc);
    kp_hid<<<(N_NODES + 127) / 128, 256, KP_SMEM>>>(hidden, Wm, bm);
    k1_msg<<<NUM_TILES, 256, K1_SMEM>>>(eidx, eattr, etime, Wm);
    k2_node<<<(HALF_N + 31) / 32, 256, K2_SMEM>>>(Wl, bl, gam, bet, out);
}